// round 2
// baseline (speedup 1.0000x reference)
#include <cuda_runtime.h>
#include <cuda_bf16.h>
#include <cstdint>

// GCN: logits = GCNConv3( relu(LN(GCNConv2( relu(LN(GCNConv1(x))) ))) )
// GCNConv(x) = segment_sum_dst( (x@W)[src] * dinvs[src]*dinvs[dst] ) + (x@W)*dinv + b
//
// CSR built per call (counts -> scan -> fill packed {src,coeff}); each layer is a
// warp-per-node gather-reduce fused with bias + LayerNorm + ReLU + next GEMM.
// NOTE: device-global scratch is referenced ONLY inside device code (passing a
// __device__ symbol as a host-side kernel arg yields a bogus address).

#define N_MAX 100000
#define E_MAX 3200000
#define IN_CH 128
#define HID   32
#define LN_EPS 1e-5f

// ---------------- device scratch (no allocations allowed) ----------------
__device__ int   g_cnt[N_MAX];
__device__ int   g_rowstart[N_MAX + 1];
__device__ int   g_cursor[N_MAX];
__device__ float g_dinvs[N_MAX];   // 1/sqrt(deg)
__device__ float g_dinv[N_MAX];    // 1/deg
__device__ int2  g_cw[E_MAX];      // {src, bitcast(coeff)}
__device__ float g_xw[N_MAX * HID];    // x @ W1
__device__ float g_hw2[N_MAX * HID];   // relu(LN(h1)) @ W2
__device__ float g_hw3[N_MAX * 2];     // relu(LN(h2)) @ W3

// ---------------- 0: zero counts ----------------
__global__ void zero_kernel(int n) {
    int i = blockIdx.x * blockDim.x + threadIdx.x;
    if (i < n) g_cnt[i] = 0;
}

// ---------------- 1: degree counts over dst ----------------
__global__ void count_kernel(const int* __restrict__ ei, int e) {
    int i = blockIdx.x * blockDim.x + threadIdx.x;
    if (i < e) atomicAdd(&g_cnt[ei[e + i]], 1);
}

// ---------------- 2: single-block exclusive scan + degree terms ----------------
__global__ void scan_kernel(int n) {
    __shared__ int wsum[32];
    int tid = threadIdx.x, lane = tid & 31, wid = tid >> 5;
    int carry = 0;
    for (int base = 0; base < n; base += 1024) {
        int i = base + tid;
        int v = (i < n) ? g_cnt[i] : 0;
        int x = v;
        #pragma unroll
        for (int d = 1; d < 32; d <<= 1) {
            int t = __shfl_up_sync(0xFFFFFFFFu, x, d);
            if (lane >= d) x += t;
        }
        if (lane == 31) wsum[wid] = x;
        __syncthreads();
        if (wid == 0) {
            int s = wsum[lane];
            #pragma unroll
            for (int d = 1; d < 32; d <<= 1) {
                int t = __shfl_up_sync(0xFFFFFFFFu, s, d);
                if (lane >= d) s += t;
            }
            wsum[lane] = s;
        }
        __syncthreads();
        int excl = carry + (wid > 0 ? wsum[wid - 1] : 0) + x - v;
        if (i < n) {
            g_rowstart[i] = excl;
            g_cursor[i]   = excl;
            float dg = (float)v + 1.0f;
            g_dinvs[i] = rsqrtf(dg);
            g_dinv[i]  = 1.0f / dg;
        }
        int tot = wsum[31];
        __syncthreads();
        carry += tot;
    }
    if (tid == 0) g_rowstart[n] = carry;
}

// ---------------- 3: fill CSR with packed {src, coeff} ----------------
__global__ void fill_kernel(const int* __restrict__ ei, int e) {
    int i = blockIdx.x * blockDim.x + threadIdx.x;
    if (i < e) {
        int s = ei[i];
        int d = ei[e + i];
        int p = atomicAdd(&g_cursor[d], 1);
        float wt = g_dinvs[s] * g_dinvs[d];
        g_cw[p] = make_int2(s, __float_as_int(wt));
    }
}

// ---------------- 4: GEMM1  g_xw = x[n,128] @ W1[128,32] ----------------
// block 256 threads, tile 128 nodes; thread computes 4 nodes x 4 channels.
__global__ void gemm1_kernel(const float* __restrict__ x,
                             const float* __restrict__ W1, int n) {
    __shared__ float Ws[128 * 32];
    __shared__ float xs[128 * 33];
    int tid = threadIdx.x;
    for (int i = tid; i < 128 * 32; i += 256) Ws[i] = W1[i];

    int tx = tid & 7;    // channel group: tx*4 .. tx*4+3
    int ty = tid >> 3;   // node group:    ty*4 .. ty*4+3 (within block)
    int wid = tid >> 5, lane = tid & 31;
    int nodeBase = blockIdx.x * 128;

    float acc[4][4];
    #pragma unroll
    for (int i = 0; i < 4; i++)
        #pragma unroll
        for (int j = 0; j < 4; j++) acc[i][j] = 0.f;

    for (int kc = 0; kc < 4; kc++) {
        __syncthreads();
        for (int r = wid; r < 128; r += 8) {
            int gn = nodeBase + r;
            float v = 0.f;
            if (gn < n) v = x[gn * IN_CH + kc * 32 + lane];
            xs[r * 33 + lane] = v;
        }
        __syncthreads();
        #pragma unroll
        for (int k = 0; k < 32; k++) {
            float4 wv = *(const float4*)&Ws[(kc * 32 + k) * 32 + tx * 4];
            float xv[4];
            #pragma unroll
            for (int i = 0; i < 4; i++) xv[i] = xs[(ty * 4 + i) * 33 + k];
            #pragma unroll
            for (int i = 0; i < 4; i++) {
                acc[i][0] = fmaf(xv[i], wv.x, acc[i][0]);
                acc[i][1] = fmaf(xv[i], wv.y, acc[i][1]);
                acc[i][2] = fmaf(xv[i], wv.z, acc[i][2]);
                acc[i][3] = fmaf(xv[i], wv.w, acc[i][3]);
            }
        }
    }
    #pragma unroll
    for (int i = 0; i < 4; i++) {
        int gn = nodeBase + ty * 4 + i;
        if (gn < n) {
            float4 r;
            r.x = acc[i][0]; r.y = acc[i][1]; r.z = acc[i][2]; r.w = acc[i][3];
            *(float4*)&g_xw[gn * HID + tx * 4] = r;
        }
    }
}

// ---------------- 5/6: CSR aggregate + self + bias + LN + ReLU + next GEMM ----
// MODE 0: in = g_xw,  out = g_hw2 via W2[32,32]
// MODE 1: in = g_hw2, out = g_hw3 via W3[32,2]
template <int MODE>
__global__ void agg_kernel(const float* __restrict__ b,
                           const float* __restrict__ g,
                           const float* __restrict__ be,
                           const float* __restrict__ Wn, int n) {
    const float* __restrict__ xw = (MODE == 0) ? g_xw : g_hw2;
    __shared__ float Wns[32 * 32];
    int tid = threadIdx.x, lane = tid & 31, wid = tid >> 5;
    int nload = (MODE == 0) ? 1024 : 64;
    for (int i = tid; i < nload; i += blockDim.x) Wns[i] = Wn[i];
    __syncthreads();

    int node = blockIdx.x * 8 + wid;
    if (node >= n) return;

    int rs = g_rowstart[node];
    int re = g_rowstart[node + 1];

    float acc = 0.f;
    int base = rs;
    // full chunks of 32 edges: cooperative coalesced int2 load + shfl broadcast
    for (; base + 32 <= re; base += 32) {
        int2 cw = g_cw[base + lane];
        float a0 = 0.f, a1 = 0.f, a2 = 0.f, a3 = 0.f;
        #pragma unroll
        for (int j = 0; j < 32; j += 4) {
            int   s0 = __shfl_sync(0xFFFFFFFFu, cw.x, j + 0);
            float w0 = __int_as_float(__shfl_sync(0xFFFFFFFFu, cw.y, j + 0));
            int   s1 = __shfl_sync(0xFFFFFFFFu, cw.x, j + 1);
            float w1 = __int_as_float(__shfl_sync(0xFFFFFFFFu, cw.y, j + 1));
            int   s2 = __shfl_sync(0xFFFFFFFFu, cw.x, j + 2);
            float w2 = __int_as_float(__shfl_sync(0xFFFFFFFFu, cw.y, j + 2));
            int   s3 = __shfl_sync(0xFFFFFFFFu, cw.x, j + 3);
            float w3 = __int_as_float(__shfl_sync(0xFFFFFFFFu, cw.y, j + 3));
            a0 = fmaf(w0, xw[s0 * HID + lane], a0);
            a1 = fmaf(w1, xw[s1 * HID + lane], a1);
            a2 = fmaf(w2, xw[s2 * HID + lane], a2);
            a3 = fmaf(w3, xw[s3 * HID + lane], a3);
        }
        acc += (a0 + a1) + (a2 + a3);
    }
    // tail
    if (base < re) {
        int idx = base + lane;
        int2 cw = (idx < re) ? g_cw[idx] : make_int2(0, 0);
        int m = re - base;
        for (int j = 0; j < m; j++) {
            int   s  = __shfl_sync(0xFFFFFFFFu, cw.x, j);
            float wt = __int_as_float(__shfl_sync(0xFFFFFFFFu, cw.y, j));
            acc = fmaf(wt, xw[s * HID + lane], acc);
        }
    }

    // self loop + bias
    acc = fmaf(xw[node * HID + lane], g_dinv[node], acc);
    acc += b[lane];

    // LayerNorm over the 32 lanes
    float s = acc;
    #pragma unroll
    for (int d = 16; d; d >>= 1) s += __shfl_xor_sync(0xFFFFFFFFu, s, d);
    float mu = s * (1.0f / 32.0f);
    float diff = acc - mu;
    float v2 = diff * diff;
    #pragma unroll
    for (int d = 16; d; d >>= 1) v2 += __shfl_xor_sync(0xFFFFFFFFu, v2, d);
    float var = v2 * (1.0f / 32.0f);
    float y = diff * rsqrtf(var + LN_EPS) * g[lane] + be[lane];
    float h = fmaxf(y, 0.f);

    if (MODE == 0) {
        // h @ W2: lane c accumulates sum_k h_k * W2[k][c]
        float o0 = 0.f, o1 = 0.f;
        #pragma unroll
        for (int k = 0; k < 32; k += 2) {
            float h0 = __shfl_sync(0xFFFFFFFFu, h, k);
            float h1 = __shfl_sync(0xFFFFFFFFu, h, k + 1);
            o0 = fmaf(h0, Wns[k * 32 + lane], o0);
            o1 = fmaf(h1, Wns[(k + 1) * 32 + lane], o1);
        }
        g_hw2[node * HID + lane] = o0 + o1;
    } else {
        // h @ W3[32,2] -> two warp reductions
        float p0 = h * Wns[lane * 2 + 0];
        float p1 = h * Wns[lane * 2 + 1];
        #pragma unroll
        for (int d = 16; d; d >>= 1) {
            p0 += __shfl_xor_sync(0xFFFFFFFFu, p0, d);
            p1 += __shfl_xor_sync(0xFFFFFFFFu, p1, d);
        }
        if (lane == 0) {
            float2 r; r.x = p0; r.y = p1;
            *(float2*)&g_hw3[node * 2] = r;
        }
    }
}

// ---------------- 7: final conv (OUT=2): agg hw3 + self + b3 ----------------
__global__ void final_kernel(const float* __restrict__ b3,
                             float* __restrict__ out, int n) {
    int tid = threadIdx.x, lane = tid & 31, wid = tid >> 5;
    int node = blockIdx.x * 8 + wid;
    if (node >= n) return;
    int rs = g_rowstart[node];
    int re = g_rowstart[node + 1];
    float a0 = 0.f, a1 = 0.f;
    for (int idx = rs + lane; idx < re; idx += 32) {
        int2 cw = g_cw[idx];
        float wt = __int_as_float(cw.y);
        float2 v = *(const float2*)&g_hw3[cw.x * 2];
        a0 = fmaf(wt, v.x, a0);
        a1 = fmaf(wt, v.y, a1);
    }
    #pragma unroll
    for (int d = 16; d; d >>= 1) {
        a0 += __shfl_xor_sync(0xFFFFFFFFu, a0, d);
        a1 += __shfl_xor_sync(0xFFFFFFFFu, a1, d);
    }
    if (lane == 0) {
        float2 self = *(const float2*)&g_hw3[node * 2];
        float di = g_dinv[node];
        out[node * 2 + 0] = a0 + self.x * di + b3[0];
        out[node * 2 + 1] = a1 + self.y * di + b3[1];
    }
}

// ---------------- launch ----------------
extern "C" void kernel_launch(void* const* d_in, const int* in_sizes, int n_in,
                              void* d_out, int out_size) {
    const float* x   = (const float*)d_in[0];
    const int*   ei  = (const int*)d_in[1];
    const float* W1  = (const float*)d_in[2];
    const float* b1  = (const float*)d_in[3];
    const float* g1  = (const float*)d_in[4];
    const float* be1 = (const float*)d_in[5];
    const float* W2  = (const float*)d_in[6];
    const float* b2  = (const float*)d_in[7];
    const float* g2  = (const float*)d_in[8];
    const float* be2 = (const float*)d_in[9];
    const float* W3  = (const float*)d_in[10];
    const float* b3  = (const float*)d_in[11];
    float* out = (float*)d_out;

    int n = in_sizes[0] / IN_CH;   // 100000
    int e = in_sizes[1] / 2;       // 3200000

    zero_kernel<<<(n + 255) / 256, 256>>>(n);
    count_kernel<<<(e + 255) / 256, 256>>>(ei, e);
    scan_kernel<<<1, 1024>>>(n);
    fill_kernel<<<(e + 255) / 256, 256>>>(ei, e);
    gemm1_kernel<<<(n + 127) / 128, 256>>>(x, W1, n);
    agg_kernel<0><<<(n + 7) / 8, 256>>>(b1, g1, be1, W2, n);
    agg_kernel<1><<<(n + 7) / 8, 256>>>(b2, g2, be2, W3, n);
    final_kernel<<<(n + 7) / 8, 256>>>(b3, out, n);
}

// round 3
// speedup vs baseline: 1.3352x; 1.3352x over previous
#include <cuda_runtime.h>
#include <cuda_bf16.h>
#include <cstdint>

// GCN with folded normalization:
//   xw'[v] = (x@W)[v] * dinvs[v]
//   GCNout[d] = dinvs[d] * ( sum_{edges s->d} xw'[s] + xw'[d] ) + b
// CSR stores src indices only. Each layer: warp-per-node gather-reduce fused
// with bias + LayerNorm + ReLU + next GEMM + prescale-by-dinvs epilogue.

#define N_MAX 100000
#define E_MAX 3200000
#define IN_CH 128
#define HID   32
#define LN_EPS 1e-5f
#define SCAN_B 1024

// ---------------- device scratch ----------------
__device__ int   g_cnt[N_MAX];
__device__ int   g_rowstart[N_MAX + 1];
__device__ int   g_cursor[N_MAX];
__device__ float g_dinvs[N_MAX];     // 1/sqrt(deg)
__device__ int   g_src[E_MAX];       // CSR src indices (dst-keyed)
__device__ int   g_bsum[128];
__device__ int   g_boff[128];
__device__ float g_xw[N_MAX * HID];  // prescaled (x@W1)*dinvs
__device__ float g_hw2[N_MAX * HID]; // prescaled (h1@W2)*dinvs
__device__ float g_hw3[N_MAX * 2];   // prescaled (h2@W3)*dinvs

// ---------------- 0: zero counts ----------------
__global__ void zero_kernel(int n) {
    int i = blockIdx.x * blockDim.x + threadIdx.x;
    if (i < n) g_cnt[i] = 0;
}

// ---------------- 1: degree counts over dst ----------------
__global__ void count_kernel(const int* __restrict__ ei, int e) {
    int i = blockIdx.x * blockDim.x + threadIdx.x;
    if (i < e) atomicAdd(&g_cnt[ei[e + i]], 1);
}

// ---------------- 2a: per-block sums of g_cnt ----------------
__global__ void blocksum_kernel(int n) {
    __shared__ int ws[32];
    int tid = threadIdx.x, lane = tid & 31, wid = tid >> 5;
    int i = blockIdx.x * SCAN_B + tid;
    int v = (i < n) ? g_cnt[i] : 0;
    int s = v;
    #pragma unroll
    for (int d = 16; d; d >>= 1) s += __shfl_xor_sync(0xFFFFFFFFu, s, d);
    if (lane == 0) ws[wid] = s;
    __syncthreads();
    if (wid == 0) {
        int t = ws[lane];
        #pragma unroll
        for (int d = 16; d; d >>= 1) t += __shfl_xor_sync(0xFFFFFFFFu, t, d);
        if (lane == 0) g_bsum[blockIdx.x] = t;
    }
}

// ---------------- 2b: scan block sums (nb <= 128) ----------------
__global__ void bscan_kernel(int nb, int n) {
    __shared__ int ws[4];
    int tid = threadIdx.x, lane = tid & 31, wid = tid >> 5;
    int v = (tid < nb) ? g_bsum[tid] : 0;
    int x = v;
    #pragma unroll
    for (int d = 1; d < 32; d <<= 1) {
        int t = __shfl_up_sync(0xFFFFFFFFu, x, d);
        if (lane >= d) x += t;
    }
    if (lane == 31) ws[wid] = x;
    __syncthreads();
    int off = 0;
    #pragma unroll
    for (int w = 0; w < 4; w++) if (w < wid) off += ws[w];
    int incl = x + off;
    if (tid < nb) g_boff[tid] = incl - v;
    if (tid == nb - 1) g_rowstart[n] = incl;
}

// ---------------- 2c: local exclusive scan + degree terms ----------------
__global__ void scan2_kernel(int n) {
    __shared__ int wsum[32];
    int tid = threadIdx.x, lane = tid & 31, wid = tid >> 5;
    int i = blockIdx.x * SCAN_B + tid;
    int v = (i < n) ? g_cnt[i] : 0;
    int x = v;
    #pragma unroll
    for (int d = 1; d < 32; d <<= 1) {
        int t = __shfl_up_sync(0xFFFFFFFFu, x, d);
        if (lane >= d) x += t;
    }
    if (lane == 31) wsum[wid] = x;
    __syncthreads();
    if (wid == 0) {
        int s = wsum[lane];
        #pragma unroll
        for (int d = 1; d < 32; d <<= 1) {
            int t = __shfl_up_sync(0xFFFFFFFFu, s, d);
            if (lane >= d) s += t;
        }
        wsum[lane] = s;
    }
    __syncthreads();
    if (i < n) {
        int excl = g_boff[blockIdx.x] + (wid > 0 ? wsum[wid - 1] : 0) + x - v;
        g_rowstart[i] = excl;
        g_cursor[i]   = excl;
        g_dinvs[i] = rsqrtf((float)v + 1.0f);
    }
}

// ---------------- 3: fill CSR (src only) ----------------
__global__ void fill_kernel(const int* __restrict__ ei, int e) {
    int i = blockIdx.x * blockDim.x + threadIdx.x;
    if (i < e) {
        int s = ei[i];
        int d = ei[e + i];
        int p = atomicAdd(&g_cursor[d], 1);
        g_src[p] = s;
    }
}

// ---------------- 4: GEMM1  g_xw = (x @ W1) * dinvs ----------------
__global__ void gemm1_kernel(const float* __restrict__ x,
                             const float* __restrict__ W1, int n) {
    __shared__ float Ws[128 * 32];
    __shared__ float xs[128 * 33];
    int tid = threadIdx.x;
    for (int i = tid; i < 128 * 32; i += 256) Ws[i] = W1[i];

    int tx = tid & 7;    // channel group tx*4..+3
    int ty = tid >> 3;   // node group   ty*4..+3
    int wid = tid >> 5, lane = tid & 31;
    int nodeBase = blockIdx.x * 128;

    float acc[4][4];
    #pragma unroll
    for (int i = 0; i < 4; i++)
        #pragma unroll
        for (int j = 0; j < 4; j++) acc[i][j] = 0.f;

    for (int kc = 0; kc < 4; kc++) {
        __syncthreads();
        for (int r = wid; r < 128; r += 8) {
            int gn = nodeBase + r;
            float v = 0.f;
            if (gn < n) v = x[gn * IN_CH + kc * 32 + lane];
            xs[r * 33 + lane] = v;
        }
        __syncthreads();
        #pragma unroll
        for (int k = 0; k < 32; k++) {
            float4 wv = *(const float4*)&Ws[(kc * 32 + k) * 32 + tx * 4];
            float xv[4];
            #pragma unroll
            for (int i = 0; i < 4; i++) xv[i] = xs[(ty * 4 + i) * 33 + k];
            #pragma unroll
            for (int i = 0; i < 4; i++) {
                acc[i][0] = fmaf(xv[i], wv.x, acc[i][0]);
                acc[i][1] = fmaf(xv[i], wv.y, acc[i][1]);
                acc[i][2] = fmaf(xv[i], wv.z, acc[i][2]);
                acc[i][3] = fmaf(xv[i], wv.w, acc[i][3]);
            }
        }
    }
    #pragma unroll
    for (int i = 0; i < 4; i++) {
        int gn = nodeBase + ty * 4 + i;
        if (gn < n) {
            float ds = g_dinvs[gn];
            float4 r;
            r.x = acc[i][0] * ds; r.y = acc[i][1] * ds;
            r.z = acc[i][2] * ds; r.w = acc[i][3] * ds;
            *(float4*)&g_xw[gn * HID + tx * 4] = r;
        }
    }
}

// ---------------- 5/6: gather-agg + bias + LN + ReLU + next GEMM ----------
// MODE 0: in = g_xw,  out = g_hw2 via W2[32,32]  (prescaled)
// MODE 1: in = g_hw2, out = g_hw3 via W3[32,2]   (prescaled)
template <int MODE>
__global__ void agg_kernel(const float* __restrict__ b,
                           const float* __restrict__ g,
                           const float* __restrict__ be,
                           const float* __restrict__ Wn, int n) {
    const float* __restrict__ xw = (MODE == 0) ? g_xw : g_hw2;
    __shared__ float Wns[32 * 32];
    int tid = threadIdx.x, lane = tid & 31, wid = tid >> 5;
    int nload = (MODE == 0) ? 1024 : 64;
    for (int i = tid; i < nload; i += blockDim.x) Wns[i] = Wn[i];
    __syncthreads();

    int node = blockIdx.x * 8 + wid;
    if (node >= n) return;

    int rs = g_rowstart[node];
    int re = g_rowstart[node + 1];

    float acc = 0.f;
    int base = rs;
    for (; base + 32 <= re; base += 32) {
        int sidx = g_src[base + lane];
        float a0 = 0.f, a1 = 0.f, a2 = 0.f, a3 = 0.f;
        #pragma unroll
        for (int j = 0; j < 32; j += 4) {
            int s0 = __shfl_sync(0xFFFFFFFFu, sidx, j + 0);
            int s1 = __shfl_sync(0xFFFFFFFFu, sidx, j + 1);
            int s2 = __shfl_sync(0xFFFFFFFFu, sidx, j + 2);
            int s3 = __shfl_sync(0xFFFFFFFFu, sidx, j + 3);
            a0 += xw[s0 * HID + lane];
            a1 += xw[s1 * HID + lane];
            a2 += xw[s2 * HID + lane];
            a3 += xw[s3 * HID + lane];
        }
        acc += (a0 + a1) + (a2 + a3);
    }
    if (base < re) {
        int idx = base + lane;
        int sidx = (idx < re) ? g_src[idx] : 0;
        int m = re - base;
        for (int j = 0; j < m; j++) {
            int s = __shfl_sync(0xFFFFFFFFu, sidx, j);
            acc += xw[s * HID + lane];
        }
    }

    // fold self loop, scale by dinvs[dst], add bias
    float ds = g_dinvs[node];
    acc = (acc + xw[node * HID + lane]) * ds + b[lane];

    // LayerNorm over the 32 lanes
    float s = acc;
    #pragma unroll
    for (int d = 16; d; d >>= 1) s += __shfl_xor_sync(0xFFFFFFFFu, s, d);
    float mu = s * (1.0f / 32.0f);
    float diff = acc - mu;
    float v2 = diff * diff;
    #pragma unroll
    for (int d = 16; d; d >>= 1) v2 += __shfl_xor_sync(0xFFFFFFFFu, v2, d);
    float var = v2 * (1.0f / 32.0f);
    float y = diff * rsqrtf(var + LN_EPS) * g[lane] + be[lane];
    float h = fmaxf(y, 0.f);

    if (MODE == 0) {
        float o0 = 0.f, o1 = 0.f;
        #pragma unroll
        for (int k = 0; k < 32; k += 2) {
            float h0 = __shfl_sync(0xFFFFFFFFu, h, k);
            float h1 = __shfl_sync(0xFFFFFFFFu, h, k + 1);
            o0 = fmaf(h0, Wns[k * 32 + lane], o0);
            o1 = fmaf(h1, Wns[(k + 1) * 32 + lane], o1);
        }
        g_hw2[node * HID + lane] = (o0 + o1) * ds;
    } else {
        float p0 = h * Wns[lane * 2 + 0];
        float p1 = h * Wns[lane * 2 + 1];
        #pragma unroll
        for (int d = 16; d; d >>= 1) {
            p0 += __shfl_xor_sync(0xFFFFFFFFu, p0, d);
            p1 += __shfl_xor_sync(0xFFFFFFFFu, p1, d);
        }
        if (lane == 0) {
            float2 r; r.x = p0 * ds; r.y = p1 * ds;
            *(float2*)&g_hw3[node * 2] = r;
        }
    }
}

// ---------------- 7: final conv (OUT=2) ----------------
__global__ void final_kernel(const float* __restrict__ b3,
                             float* __restrict__ out, int n) {
    int tid = threadIdx.x, lane = tid & 31, wid = tid >> 5;
    int node = blockIdx.x * 8 + wid;
    if (node >= n) return;
    int rs = g_rowstart[node];
    int re = g_rowstart[node + 1];
    float a0 = 0.f, a1 = 0.f;
    for (int idx = rs + lane; idx < re; idx += 32) {
        float2 v = *(const float2*)&g_hw3[g_src[idx] * 2];
        a0 += v.x;
        a1 += v.y;
    }
    #pragma unroll
    for (int d = 16; d; d >>= 1) {
        a0 += __shfl_xor_sync(0xFFFFFFFFu, a0, d);
        a1 += __shfl_xor_sync(0xFFFFFFFFu, a1, d);
    }
    if (lane == 0) {
        float2 self = *(const float2*)&g_hw3[node * 2];
        float ds = g_dinvs[node];
        out[node * 2 + 0] = (a0 + self.x) * ds + b3[0];
        out[node * 2 + 1] = (a1 + self.y) * ds + b3[1];
    }
}

// ---------------- launch ----------------
extern "C" void kernel_launch(void* const* d_in, const int* in_sizes, int n_in,
                              void* d_out, int out_size) {
    const float* x   = (const float*)d_in[0];
    const int*   ei  = (const int*)d_in[1];
    const float* W1  = (const float*)d_in[2];
    const float* b1  = (const float*)d_in[3];
    const float* g1  = (const float*)d_in[4];
    const float* be1 = (const float*)d_in[5];
    const float* W2  = (const float*)d_in[6];
    const float* b2  = (const float*)d_in[7];
    const float* g2  = (const float*)d_in[8];
    const float* be2 = (const float*)d_in[9];
    const float* W3  = (const float*)d_in[10];
    const float* b3  = (const float*)d_in[11];
    float* out = (float*)d_out;

    int n = in_sizes[0] / IN_CH;   // 100000
    int e = in_sizes[1] / 2;       // 3200000
    int nb = (n + SCAN_B - 1) / SCAN_B;

    zero_kernel<<<(n + 255) / 256, 256>>>(n);
    count_kernel<<<(e + 255) / 256, 256>>>(ei, e);
    blocksum_kernel<<<nb, SCAN_B>>>(n);
    bscan_kernel<<<1, 128>>>(nb, n);
    scan2_kernel<<<nb, SCAN_B>>>(n);
    fill_kernel<<<(e + 255) / 256, 256>>>(ei, e);
    gemm1_kernel<<<(n + 127) / 128, 256>>>(x, W1, n);
    agg_kernel<0><<<(n + 7) / 8, 256>>>(b1, g1, be1, W2, n);
    agg_kernel<1><<<(n + 7) / 8, 256>>>(b2, g2, be2, W3, n);
    final_kernel<<<(n + 7) / 8, 256>>>(b3, out, n);
}